// round 2
// baseline (speedup 1.0000x reference)
#include <cuda_runtime.h>
#include <math.h>

#define BATCH  2
#define SEQ    2048
#define DIM    1024
#define VOCAB  32000
#define NLAYER 6
#define MROWS  (BATCH*SEQ)   // 4096

typedef unsigned long long u64;

// ---------------- scratch (static device globals; no allocations) ----------------
__device__ float g_xA[BATCH*SEQ*DIM];
__device__ float g_xB[BATCH*SEQ*DIM];
__device__ float g_c [BATCH*DIM*SEQ];
__device__ float g_y [BATCH*DIM*SEQ];
__device__ float g_rf[MROWS*DIM];
__device__ float g_gp[MROWS*DIM];
__device__ float g_mu[MROWS];
__device__ float g_rs[MROWS];

// ---------------- helpers ----------------
__device__ __forceinline__ float warpRed(float v) {
    #pragma unroll
    for (int o = 16; o; o >>= 1) v += __shfl_xor_sync(0xffffffffu, v, o);
    return v;
}

// packed fp32x2 FMA: d = a*b + d  (each half exact fp32 FMA; 2x fma-pipe throughput)
__device__ __forceinline__ void ffma2(u64& d, u64 a, u64 b) {
    asm("fma.rn.f32x2 %0, %1, %2, %0;" : "+l"(d) : "l"(a), "l"(b));
}

// ---------------- embed + sinusoidal PE ----------------
__global__ void k_embed(const int* __restrict__ ids, const float* __restrict__ emb,
                        float* __restrict__ x) {
    int idx = blockIdx.x * 256 + threadIdx.x;
    int d   = idx & (DIM - 1);
    int row = idx >> 10;
    int s   = row & (SEQ - 1);
    int tok = ids[row];
    float ang = (float)s * expf((float)(d & ~1) * (-9.210340371976184f / (float)DIM));
    float pe  = (d & 1) ? cosf(ang) : sinf(ang);
    x[idx] = emb[(size_t)tok * DIM + d] + pe;
}

// ---------------- per-row layernorm stats ----------------
__global__ void __launch_bounds__(256) k_lnstats(const float* __restrict__ x,
                                                 float* __restrict__ mu, float* __restrict__ rs) {
    int row = blockIdx.x;
    int t   = threadIdx.x;
    const float* p = x + (size_t)row * DIM;
    float v[4];
    float s = 0.f;
    #pragma unroll
    for (int i = 0; i < 4; i++) { v[i] = p[t + i * 256]; s += v[i]; }
    __shared__ float red[8];
    __shared__ float sh_m;
    s = warpRed(s);
    if ((t & 31) == 0) red[t >> 5] = s;
    __syncthreads();
    if (t == 0) {
        float tot = 0.f;
        #pragma unroll
        for (int i = 0; i < 8; i++) tot += red[i];
        sh_m = tot / (float)DIM;
    }
    __syncthreads();
    float m = sh_m;
    float q = 0.f;
    #pragma unroll
    for (int i = 0; i < 4; i++) { float dd = v[i] - m; q += dd * dd; }
    q = warpRed(q);
    if ((t & 31) == 0) red[t >> 5] = q;
    __syncthreads();
    if (t == 0) {
        float tot = 0.f;
        #pragma unroll
        for (int i = 0; i < 8; i++) tot += red[i];
        mu[row] = m;
        rs[row] = rsqrtf(tot / (float)DIM + 1e-5f);
    }
}

// ---------------- fused normalize + transpose (B,S,D)->(B,D,S) ----------------
__global__ void k_tn(const float* __restrict__ x, const float* __restrict__ mu,
                     const float* __restrict__ rs, const float* __restrict__ gg,
                     const float* __restrict__ bb, float* __restrict__ c) {
    __shared__ float tile[32][33];
    int b  = blockIdx.z;
    int s0 = blockIdx.x * 32;
    int d0 = blockIdx.y * 32;
    int tx = threadIdx.x, ty = threadIdx.y;
    #pragma unroll
    for (int i = 0; i < 4; i++) {
        int s = s0 + ty + i * 8;
        int r = b * SEQ + s;
        tile[ty + i * 8][tx] = (x[(size_t)r * DIM + d0 + tx] - mu[r]) * rs[r];
    }
    __syncthreads();
    #pragma unroll
    for (int i = 0; i < 4; i++) {
        int d = d0 + ty + i * 8;
        c[((size_t)(b * DIM + d)) * SEQ + s0 + tx] = tile[tx][ty + i * 8] * gg[d] + bb[d];
    }
}

// ---------------- conv chain: conv3 -> conv64 (+res) -> conv64 -> mix -> silu ----------------
__global__ void __launch_bounds__(256) k_conv(const float* __restrict__ cbuf,
                                              const float* __restrict__ local_w,
                                              const float* __restrict__ filt_w,
                                              const float* __restrict__ mix_w,
                                              float* __restrict__ ybuf, int layer) {
    int bd = blockIdx.x;
    int d  = bd & (DIM - 1);
    __shared__ float s_in[SEQ + 64];
    __shared__ float s_t [SEQ + 64];
    __shared__ float w3[4], w0[64], w1[64], smix[1];
    int t = threadIdx.x;
    if (t < 3)                  w3[t]       = local_w[((size_t)layer * DIM + d) * 3 + t];
    if (t >= 64 && t < 128)     w0[t - 64]  = filt_w[(((size_t)layer * 2 + 0) * DIM + d) * 64 + (t - 64)];
    if (t >= 128 && t < 192)    w1[t - 128] = filt_w[(((size_t)layer * 2 + 1) * DIM + d) * 64 + (t - 128)];
    if (t == 224)               smix[0]     = mix_w[layer * DIM + d];
    if (t < 32) { s_in[t] = 0.f; s_t[t] = 0.f; s_in[SEQ + 32 + t] = 0.f; s_t[SEQ + 32 + t] = 0.f; }
    const float* cp = cbuf + (size_t)bd * SEQ;
    #pragma unroll
    for (int i = 0; i < 8; i++) s_in[32 + t + i * 256] = cp[t + i * 256];
    __syncthreads();
    #pragma unroll
    for (int i = 0; i < 8; i++) {
        int tt = 32 + t + i * 256;
        s_t[tt] = s_in[tt - 1] * w3[0] + s_in[tt] * w3[1] + s_in[tt + 1] * w3[2];
    }
    __syncthreads();
    float r[8];
    #pragma unroll
    for (int i = 0; i < 8; i++) r[i] = s_in[32 + t + i * 256];
    #pragma unroll
    for (int k = 0; k < 64; k++) {
        float wv = w0[k];
        #pragma unroll
        for (int i = 0; i < 8; i++) r[i] += wv * s_t[t + i * 256 + k];
    }
    #pragma unroll
    for (int i = 0; i < 8; i++) s_in[32 + t + i * 256] = r[i];
    __syncthreads();
    float mix = smix[0];
    #pragma unroll
    for (int i = 0; i < 8; i++) r[i] = 0.f;
    #pragma unroll
    for (int k = 0; k < 64; k++) {
        float wv = w1[k];
        #pragma unroll
        for (int i = 0; i < 8; i++) r[i] += wv * s_in[t + i * 256 + k];
    }
    float* yp = ybuf + (size_t)bd * SEQ;
    #pragma unroll
    for (int i = 0; i < 8; i++) {
        float m = r[i] * mix;
        yp[t + i * 256] = m / (1.f + expf(-m));
    }
}

// ---------------- fp32 SIMT GEMM with packed f32x2 FMAs ----------------
// C[M,N] = A(MxK) * B(KxN) + bias
// AT: A stored (B,D,S): A[m,k] = A[(m>>11)*DIM*SEQ + k*SEQ + (m & 2047)]
// BT: B stored row-major (N,K)
template <bool AT, bool BT, bool BIAS>
__global__ void __launch_bounds__(256) k_gemm(const float* __restrict__ A,
                                              const float* __restrict__ Bm,
                                              const float* __restrict__ bias,
                                              float* __restrict__ C, int N, int K) {
    __shared__ float As2[8][256];   // duplicated pairs: As2[k][2m]=As2[k][2m+1]=A[m0+m,k0+k]
    __shared__ float Bs [8][128];
    int tid = threadIdx.x;
    int m0 = blockIdx.y * 128, n0 = blockIdx.x * 128;
    int row = (tid / 16) * 8, col = (tid % 16) * 8;

    u64 acc2[8][4];
    #pragma unroll
    for (int i = 0; i < 8; i++)
        #pragma unroll
        for (int j = 0; j < 4; j++) acc2[i][j] = 0ULL;

    // ---- prefetch regs ----
    float4 pa, pb;
    auto loadA = [&](int k0) {
        if (AT) {
            int k = tid >> 5, m4 = (tid & 31) * 4;
            int m = m0 + m4;
            pa = *(const float4*)(A + (size_t)(m >> 11) * DIM * SEQ
                                    + (size_t)(k0 + k) * SEQ + (m & (SEQ - 1)));
        } else {
            int m = tid >> 1, kq = (tid & 1) * 4;
            pa = *(const float4*)(A + (size_t)(m0 + m) * K + k0 + kq);
        }
    };
    auto loadB = [&](int k0) {
        if (BT) {
            int n = tid >> 1, kq = (tid & 1) * 4;
            pb = *(const float4*)(Bm + (size_t)(n0 + n) * K + k0 + kq);
        } else {
            int k = tid >> 5, n4 = (tid & 31) * 4;
            pb = *(const float4*)(Bm + (size_t)(k0 + k) * N + n0 + n4);
        }
    };
    auto storeA = [&]() {
        if (AT) {
            int k = tid >> 5, m4 = (tid & 31) * 4;
            float4 d0 = make_float4(pa.x, pa.x, pa.y, pa.y);
            float4 d1 = make_float4(pa.z, pa.z, pa.w, pa.w);
            *(float4*)&As2[k][2 * m4]     = d0;
            *(float4*)&As2[k][2 * m4 + 4] = d1;
        } else {
            int m = tid >> 1, kq = (tid & 1) * 4;
            *(float2*)&As2[kq + 0][2 * m] = make_float2(pa.x, pa.x);
            *(float2*)&As2[kq + 1][2 * m] = make_float2(pa.y, pa.y);
            *(float2*)&As2[kq + 2][2 * m] = make_float2(pa.z, pa.z);
            *(float2*)&As2[kq + 3][2 * m] = make_float2(pa.w, pa.w);
        }
    };
    auto storeB = [&]() {
        if (BT) {
            int n = tid >> 1, kq = (tid & 1) * 4;
            Bs[kq + 0][n] = pb.x; Bs[kq + 1][n] = pb.y;
            Bs[kq + 2][n] = pb.z; Bs[kq + 3][n] = pb.w;
        } else {
            int k = tid >> 5, n4 = (tid & 31) * 4;
            *(float4*)&Bs[k][n4] = pb;
        }
    };

    loadA(0); loadB(0);
    for (int k0 = 0; k0 < K; k0 += 8) {
        storeA(); storeB();
        __syncthreads();
        if (k0 + 8 < K) { loadA(k0 + 8); loadB(k0 + 8); }
        #pragma unroll
        for (int k = 0; k < 8; k++) {
            const ulonglong2* ap = (const ulonglong2*)&As2[k][2 * row];
            ulonglong2 A0 = ap[0], A1 = ap[1], A2 = ap[2], A3 = ap[3];
            const ulonglong2* bp = (const ulonglong2*)&Bs[k][col];
            ulonglong2 B0 = bp[0], B1 = bp[1];
            u64 a2[8] = {A0.x, A0.y, A1.x, A1.y, A2.x, A2.y, A3.x, A3.y};
            u64 b2[4] = {B0.x, B0.y, B1.x, B1.y};
            #pragma unroll
            for (int i = 0; i < 8; i++) {
                ffma2(acc2[i][0], a2[i], b2[0]);
                ffma2(acc2[i][1], a2[i], b2[1]);
                ffma2(acc2[i][2], a2[i], b2[2]);
                ffma2(acc2[i][3], a2[i], b2[3]);
            }
        }
        __syncthreads();
    }

    float bv[8];
    #pragma unroll
    for (int j = 0; j < 8; j++) bv[j] = BIAS ? bias[n0 + col + j] : 0.f;
    #pragma unroll
    for (int i = 0; i < 8; i++) {
        float2 p0 = *(float2*)&acc2[i][0];
        float2 p1 = *(float2*)&acc2[i][1];
        float2 p2 = *(float2*)&acc2[i][2];
        float2 p3 = *(float2*)&acc2[i][3];
        float4 o0 = make_float4(p0.x + bv[0], p0.y + bv[1], p1.x + bv[2], p1.y + bv[3]);
        float4 o1 = make_float4(p2.x + bv[4], p2.y + bv[5], p3.x + bv[6], p3.y + bv[7]);
        size_t off = (size_t)(m0 + row + i) * N + n0 + col;
        *(float4*)(C + off)     = o0;
        *(float4*)(C + off + 4) = o1;
    }
}

// ---------------- gate combine ----------------
__global__ void k_combine(const float* __restrict__ rf, const float* __restrict__ gp,
                          const float* __restrict__ orig, float* __restrict__ xo) {
    int idx = blockIdx.x * 256 + threadIdx.x;
    float gate = 1.f / (1.f + expf(-gp[idx]));
    xo[idx] = gate * rf[idx] + (1.f - gate) * orig[idx];
}

// ---------------- final LN normalize ----------------
__global__ void k_norm_rows(const float* __restrict__ x, const float* __restrict__ mu,
                            const float* __restrict__ rs, const float* __restrict__ gg,
                            const float* __restrict__ bb, float* __restrict__ o) {
    int idx = blockIdx.x * 256 + threadIdx.x;
    int d = idx & (DIM - 1);
    int row = idx >> 10;
    o[idx] = (x[idx] - mu[row]) * rs[row] * gg[d] + bb[d];
}

// ---------------- launch ----------------
extern "C" void kernel_launch(void* const* d_in, const int* in_sizes, int n_in,
                              void* d_out, int out_size) {
    const int*   ids     = (const int*)  d_in[0];
    const float* emb     = (const float*)d_in[1];
    const float* local_w = (const float*)d_in[2];
    const float* filt_w  = (const float*)d_in[3];
    const float* mix_w   = (const float*)d_in[4];
    const float* ln1_g   = (const float*)d_in[5];
    const float* ln1_b   = (const float*)d_in[6];
    const float* ref_W   = (const float*)d_in[7];
    const float* ref_b   = (const float*)d_in[8];
    const float* gate_W  = (const float*)d_in[9];
    const float* gate_b  = (const float*)d_in[10];
    const float* lnf_g   = (const float*)d_in[11];
    const float* lnf_b   = (const float*)d_in[12];
    const float* out_W   = (const float*)d_in[13];
    const float* out_b   = (const float*)d_in[14];
    float* out = (float*)d_out;

    float *xA, *xB, *cb, *yb, *rb, *gb, *mub, *rsb;
    cudaGetSymbolAddress((void**)&xA,  g_xA);
    cudaGetSymbolAddress((void**)&xB,  g_xB);
    cudaGetSymbolAddress((void**)&cb,  g_c);
    cudaGetSymbolAddress((void**)&yb,  g_y);
    cudaGetSymbolAddress((void**)&rb,  g_rf);
    cudaGetSymbolAddress((void**)&gb,  g_gp);
    cudaGetSymbolAddress((void**)&mub, g_mu);
    cudaGetSymbolAddress((void**)&rsb, g_rs);

    k_embed<<<BATCH * SEQ * DIM / 256, 256>>>(ids, emb, xA);

    float* cur = xA;
    float* nxt = xB;
    for (int l = 0; l < NLAYER; l++) {
        k_lnstats<<<MROWS, 256>>>(cur, mub, rsb);
        k_tn<<<dim3(SEQ / 32, DIM / 32, BATCH), dim3(32, 8)>>>(cur, mub, rsb,
                                                               ln1_g + l * DIM, ln1_b + l * DIM, cb);
        k_conv<<<BATCH * DIM, 256>>>(cb, local_w, filt_w, mix_w, yb, l);
        k_gemm<true,  true, true><<<dim3(DIM / 128, MROWS / 128), 256>>>(
            yb,  ref_W  + (size_t)l * DIM * DIM, ref_b  + l * DIM, rb, DIM, DIM);
        k_gemm<false, true, true><<<dim3(DIM / 128, MROWS / 128), 256>>>(
            cur, gate_W + (size_t)l * DIM * DIM, gate_b + l * DIM, gb, DIM, DIM);
        k_combine<<<MROWS * DIM / 256, 256>>>(rb, gb, cur, nxt);
        float* tmp = cur; cur = nxt; nxt = tmp;
    }

    k_lnstats<<<MROWS, 256>>>(cur, mub, rsb);
    k_norm_rows<<<MROWS * DIM / 256, 256>>>(cur, mub, rsb, lnf_g, lnf_b, cb);
    k_gemm<false, false, true><<<dim3(VOCAB / 128, MROWS / 128), 256>>>(
        cb, out_W, out_b, out, VOCAB, DIM);
}